// round 10
// baseline (speedup 1.0000x reference)
#include <cuda_runtime.h>
#include <cuda_bf16.h>
#include <cuda_fp16.h>
#include <math.h>
#include <stdint.h>

// Problem constants (fixed-shape problem)
#define NNODES 50000
#define NEDGES 800000
#define FIN    256
#define HID    256
#define NCLS   32
#define SELFW  2.0f

#define NB512  98                        // ceil(50000/512)
#define WSZ_TOT (3*256*256 + 256*32)     // all weights, fp16 split storage
#define W_OFF_H   (256*256)
#define W_OFF_OUT (3*256*256)

// ---------------- Device scratch (no allocations allowed) ----------------
__device__ int   g_deg[NNODES];
__device__ int   g_cur[NNODES];
__device__ int   g_off[NNODES + 1];
__device__ int   g_blksum[NB512];
__device__ int   g_blkoff[NB512];
__device__ __align__(16) int   g_csr_src[NEDGES];
__device__ __align__(16) float g_csr_w[NEDGES];
__device__ float g_dinv[NNODES];
__device__ float g_selfn[NNODES];
__device__ __align__(16) float  g_y[NNODES * NCLS];     // fp32 GEMM out (final layer)
__device__ __align__(16) __half g_yh[NNODES * HID];     // fp16 GEMM out / gather plane
__device__ __align__(16) __half g_h[NNODES * HID];      // fp16 activations (GEMM A input)
__device__ __align__(16) __half g_Whi[WSZ_TOT];         // weight hi split (fp16)
__device__ __align__(16) __half g_Wlo[WSZ_TOT];         // weight lo split (fp16)

// ---------------- small helpers ----------------
__device__ __forceinline__ uint32_t sptr(const void* p) {
    return (uint32_t)__cvta_generic_to_shared(p);
}
__device__ __forceinline__ void ldsm_x4(uint32_t& r0, uint32_t& r1, uint32_t& r2, uint32_t& r3,
                                        uint32_t addr) {
    asm volatile("ldmatrix.sync.aligned.m8n8.x4.shared.b16 {%0,%1,%2,%3}, [%4];\n"
                 : "=r"(r0), "=r"(r1), "=r"(r2), "=r"(r3) : "r"(addr));
}
__device__ __forceinline__ void ldsm_x4_t(uint32_t& r0, uint32_t& r1, uint32_t& r2, uint32_t& r3,
                                          uint32_t addr) {
    asm volatile("ldmatrix.sync.aligned.m8n8.x4.trans.shared.b16 {%0,%1,%2,%3}, [%4];\n"
                 : "=r"(r0), "=r"(r1), "=r"(r2), "=r"(r3) : "r"(addr));
}
__device__ __forceinline__ void mma_f16(float& c0, float& c1, float& c2, float& c3,
                                        uint32_t a0, uint32_t a1, uint32_t a2, uint32_t a3,
                                        uint32_t b0, uint32_t b1) {
    asm volatile("mma.sync.aligned.m16n8k16.row.col.f32.f16.f16.f32 "
                 "{%0,%1,%2,%3}, {%4,%5,%6,%7}, {%8,%9}, {%0,%1,%2,%3};\n"
                 : "+f"(c0), "+f"(c1), "+f"(c2), "+f"(c3)
                 : "r"(a0), "r"(a1), "r"(a2), "r"(a3), "r"(b0), "r"(b1));
}
__device__ __forceinline__ void cp16(uint32_t saddr, const void* g, int sz) {
    asm volatile("cp.async.cg.shared.global [%0], [%1], 16, %2;\n"
                 :: "r"(saddr), "l"(g), "r"(sz));
}
__device__ __forceinline__ void cp_commit() { asm volatile("cp.async.commit_group;\n"); }
template <int N>
__device__ __forceinline__ void cp_wait() { asm volatile("cp.async.wait_group %0;\n" :: "n"(N)); }

// ---------------- fp32 -> fp16 hi/lo split ----------------
__device__ __forceinline__ void wsplit2(float a, float b, __half2& h2, __half2& l2) {
    __half ha = __float2half_rn(a);
    __half hb = __float2half_rn(b);
    __half la = __float2half_rn(a - __half2float(ha));
    __half lb = __float2half_rn(b - __half2float(hb));
    h2 = __half2(ha, hb);
    l2 = __half2(la, lb);
}

// ---------------- weight split (all weights, one kernel) ----------------
__global__ void k_split_w_all(const float* __restrict__ Win,
                              const float* __restrict__ Wh,
                              const float* __restrict__ Wout) {
    int i = blockIdx.x * blockDim.x + threadIdx.x;   // vec4 index
    int e4 = i * 4;
    if (e4 >= WSZ_TOT) return;
    const float* src;
    int off;
    if (e4 < W_OFF_H)        { src = Win;  off = e4; }
    else if (e4 < W_OFF_OUT) { src = Wh;   off = e4 - W_OFF_H; }
    else                     { src = Wout; off = e4 - W_OFF_OUT; }
    float4 v = *reinterpret_cast<const float4*>(src + off);
    __half2 h0, l0, h1, l1;
    wsplit2(v.x, v.y, h0, l0);
    wsplit2(v.z, v.w, h1, l1);
    __half2* H = reinterpret_cast<__half2*>(g_Whi);
    __half2* L = reinterpret_cast<__half2*>(g_Wlo);
    H[i * 2] = h0; H[i * 2 + 1] = h1;
    L[i * 2] = l0; L[i * 2 + 1] = l1;
}

// ---------------- x -> fp16 activations ----------------
__global__ void k_cvt_x(const float* __restrict__ src, int n) {
    int i = blockIdx.x * blockDim.x + threadIdx.x;
    if (i * 4 >= n) return;
    float4 v = reinterpret_cast<const float4*>(src)[i];
    __half2* H = reinterpret_cast<__half2*>(g_h);
    H[i * 2]     = __floats2half2_rn(v.x, v.y);
    H[i * 2 + 1] = __floats2half2_rn(v.z, v.w);
}

// ---------------- Precompute: degree, norm, CSR ----------------
__global__ void k_zero_counts() {
    int i = blockIdx.x * blockDim.x + threadIdx.x;
    if (i < NNODES) { g_deg[i] = 0; g_cur[i] = 0; }
}

__global__ void k_hist(const int* __restrict__ dst) {
    int e = blockIdx.x * blockDim.x + threadIdx.x;
    if (e < NEDGES) atomicAdd(&g_deg[dst[e]], 1);
}

__global__ void k_blksum() {
    __shared__ int wsum[16];
    int b = blockIdx.x, tid = threadIdx.x;
    int i = b * 512 + tid;
    int v = 0;
    if (i < NNODES) {
        v = g_deg[i];
        float d  = (float)v + SELFW;
        float di = rsqrtf(d);
        g_dinv[i]  = di;
        g_selfn[i] = SELFW * di * di;
    }
    int s = v;
    #pragma unroll
    for (int o = 16; o > 0; o >>= 1) s += __shfl_down_sync(0xffffffffu, s, o);
    if ((tid & 31) == 0) wsum[tid >> 5] = s;
    __syncthreads();
    if (tid < 16) {
        int t = wsum[tid];
        #pragma unroll
        for (int o = 8; o > 0; o >>= 1) t += __shfl_down_sync(0xffffu, t, o);
        if (tid == 0) g_blksum[b] = t;
    }
}

__global__ void k_blkscan() {
    __shared__ int wtot[4];
    int tid = threadIdx.x, lane = tid & 31, wid = tid >> 5;
    int v = (tid < NB512) ? g_blksum[tid] : 0;
    int x = v;
    #pragma unroll
    for (int o = 1; o < 32; o <<= 1) {
        int y = __shfl_up_sync(0xffffffffu, x, o);
        if (lane >= o) x += y;
    }
    if (lane == 31) wtot[wid] = x;
    __syncthreads();
    int woff = 0;
    for (int w = 0; w < wid; w++) woff += wtot[w];
    int incl = x + woff;
    if (tid < NB512) g_blkoff[tid] = incl - v;
    if (tid == NB512 - 1) g_off[NNODES] = incl;
}

__global__ void k_scanfinal() {
    __shared__ int wsum[16];
    int b = blockIdx.x, tid = threadIdx.x, lane = tid & 31, wid = tid >> 5;
    int i = b * 512 + tid;
    int v = (i < NNODES) ? g_deg[i] : 0;
    int x = v;
    #pragma unroll
    for (int o = 1; o < 32; o <<= 1) {
        int y = __shfl_up_sync(0xffffffffu, x, o);
        if (lane >= o) x += y;
    }
    if (lane == 31) wsum[wid] = x;
    __syncthreads();
    if (wid == 0) {
        int s = (lane < 16) ? wsum[lane] : 0;
        #pragma unroll
        for (int o = 1; o < 16; o <<= 1) {
            int y = __shfl_up_sync(0xffffffffu, s, o);
            if (lane >= o) s += y;
        }
        if (lane < 16) wsum[lane] = s;
    }
    __syncthreads();
    int woff = (wid == 0) ? 0 : wsum[wid - 1];
    if (i < NNODES) g_off[i] = g_blkoff[b] + woff + (x - v);
}

__global__ void k_fill_csr(const int* __restrict__ src, const int* __restrict__ dst) {
    int e = blockIdx.x * blockDim.x + threadIdx.x;
    if (e < NEDGES) {
        int s = src[e], d = dst[e];
        int p = atomicAdd(&g_cur[d], 1);
        int idx = g_off[d] + p;
        g_csr_src[idx] = s;
        g_csr_w[idx]   = g_dinv[s] * g_dinv[d];
    }
}

// ---------------- fp16 2-term split GEMM, cp.async 2-stage pipeline (big layers) -------
// C_fp16[Nrows,256] = A_fp16[Nrows,256] @ (Whi + Wlo); BM=128, BN=128, 256 thr.
__global__ void __launch_bounds__(256) mma_gemm_p(int Nrows, int K, int Mcols, int woff) {
    constexpr int BM = 128, BN = 128, BK = 32;
    constexpr int WM = 64, WN = 32;
    constexpr int WARPS_N = BN / WN;          // 4
    constexpr int FM = WM / 16;               // 4
    constexpr int FN = WN / 8;                // 4
    constexpr int ASTR = BK + 8;              // 40 halves (80B rows, 16B aligned)
    constexpr int BSTR = BN + 8;              // 136 halves
    constexpr int A_ST = BM * ASTR;           // 5120 halves per stage
    constexpr int B_ST = BK * BSTR;           // 4352 halves per stage-plane

    extern __shared__ __half sm[];
    __half* Asm = sm;                         // [st][BM][ASTR]
    __half* Bsm = sm + 2 * A_ST;              // [st][plane][BK][BSTR]

    const int tid  = threadIdx.x;
    const int lane = tid & 31;
    const int w    = tid >> 5;
    const int wm0  = (w / WARPS_N) * WM;
    const int wn0  = (w % WARPS_N) * WN;
    const int row0 = blockIdx.y * BM;
    const int col0 = blockIdx.x * BN;

    const __half* __restrict__ Whi = g_Whi + woff;
    const __half* __restrict__ Wlo = g_Wlo + woff;

    float acc[FM][FN][4];
    #pragma unroll
    for (int i = 0; i < FM; i++)
        #pragma unroll
        for (int j = 0; j < FN; j++)
            #pragma unroll
            for (int r = 0; r < 4; r++) acc[i][j][r] = 0.f;

    const int NT = K / BK;   // 8

    auto issue = [&](int kt, int st) {
        int k0 = kt * BK;
        // A: 128 rows x 4 vec8 = 512 units, 2 iters
        #pragma unroll
        for (int it = 0; it < 2; it++) {
            int u = tid + it * 256;
            int r = u >> 2, q = u & 3;
            int grow = row0 + r;
            int sz = (grow < Nrows) ? 16 : 0;
            long ga = (long)((grow < Nrows) ? grow : 0) * K + k0 + q * 8;
            cp16(sptr(Asm + st * A_ST + r * ASTR + q * 8), g_h + ga, sz);
        }
        // B planes: 32 rows x 16 vec8 = 512 units each, 2 iters each
        #pragma unroll
        for (int it = 0; it < 2; it++) {
            int u = tid + it * 256;
            int r = u >> 4, q = u & 15;
            long gb = (long)(k0 + r) * Mcols + col0 + q * 8;
            cp16(sptr(Bsm + (st * 2 + 0) * B_ST + r * BSTR + q * 8), Whi + gb, 16);
            cp16(sptr(Bsm + (st * 2 + 1) * B_ST + r * BSTR + q * 8), Wlo + gb, 16);
        }
        cp_commit();
    };

    issue(0, 0);

    #pragma unroll 1
    for (int kt = 0; kt < NT; kt++) {
        int st = kt & 1;
        if (kt + 1 < NT) { issue(kt + 1, st ^ 1); cp_wait<1>(); }
        else             { cp_wait<0>(); }
        __syncthreads();

        #pragma unroll
        for (int k16 = 0; k16 < BK / 16; k16++) {
            uint32_t a[FM][4], bh[FN][2], bl[FN][2];
            const int arow = lane & 15;
            const int acol = k16 * 16 + ((lane >> 4) << 3);
            #pragma unroll
            for (int fm = 0; fm < FM; fm++)
                ldsm_x4(a[fm][0], a[fm][1], a[fm][2], a[fm][3],
                        sptr(Asm + st * A_ST + (wm0 + fm * 16 + arow) * ASTR + acol));
            const int brow = k16 * 16 + (lane & 15);
            const int bcofs = (lane >> 4) << 3;
            #pragma unroll
            for (int p = 0; p < FN / 2; p++) {
                ldsm_x4_t(bh[p * 2][0], bh[p * 2][1], bh[p * 2 + 1][0], bh[p * 2 + 1][1],
                          sptr(Bsm + (st * 2 + 0) * B_ST + brow * BSTR + wn0 + p * 16 + bcofs));
                ldsm_x4_t(bl[p * 2][0], bl[p * 2][1], bl[p * 2 + 1][0], bl[p * 2 + 1][1],
                          sptr(Bsm + (st * 2 + 1) * B_ST + brow * BSTR + wn0 + p * 16 + bcofs));
            }
            #pragma unroll
            for (int fm = 0; fm < FM; fm++)
                #pragma unroll
                for (int fn = 0; fn < FN; fn++) {
                    float* c = acc[fm][fn];
                    mma_f16(c[0], c[1], c[2], c[3],
                            a[fm][0], a[fm][1], a[fm][2], a[fm][3],
                            bh[fn][0], bh[fn][1]);
                    mma_f16(c[0], c[1], c[2], c[3],
                            a[fm][0], a[fm][1], a[fm][2], a[fm][3],
                            bl[fn][0], bl[fn][1]);
                }
        }
        __syncthreads();
    }

    // epilogue -> fp16 g_yh
    #pragma unroll
    for (int fm = 0; fm < FM; fm++) {
        int grow0 = row0 + wm0 + fm * 16 + (lane >> 2);
        #pragma unroll
        for (int fn = 0; fn < FN; fn++) {
            int gcol = col0 + wn0 + fn * 8 + (lane & 3) * 2;
            float* c = acc[fm][fn];
            if (grow0 < Nrows)
                *reinterpret_cast<__half2*>(&g_yh[(long)grow0 * Mcols + gcol]) =
                    __floats2half2_rn(c[0], c[1]);
            if (grow0 + 8 < Nrows)
                *reinterpret_cast<__half2*>(&g_yh[(long)(grow0 + 8) * Mcols + gcol]) =
                    __floats2half2_rn(c[2], c[3]);
        }
    }
}

// ---------------- fp16 2-term split GEMM (sync smem; out layer, fp32 out) --------------
template <int BM, int BN, int WM, int WN>
__global__ void mma_gemm_s(int Nrows, int K, int Mcols, int woff) {
    constexpr int WARPS_M = BM / WM;
    constexpr int WARPS_N = BN / WN;
    constexpr int THREADS = WARPS_M * WARPS_N * 32;
    constexpr int FM = WM / 16;
    constexpr int FN = WN / 8;
    constexpr int BK = 32;

    __shared__ __half As[BM][BK + 8];
    __shared__ __half Bs[2][BK][BN + 8];

    const int tid  = threadIdx.x;
    const int lane = tid & 31;
    const int w    = tid >> 5;
    const int wm0  = (w / WARPS_N) * WM;
    const int wn0  = (w % WARPS_N) * WN;
    const int row0 = blockIdx.y * BM;
    const int col0 = blockIdx.x * BN;

    const __half* __restrict__ Whi = g_Whi + woff;
    const __half* __restrict__ Wlo = g_Wlo + woff;

    float acc[FM][FN][4];
    #pragma unroll
    for (int i = 0; i < FM; i++)
        #pragma unroll
        for (int j = 0; j < FN; j++)
            #pragma unroll
            for (int r = 0; r < 4; r++) acc[i][j][r] = 0.f;

    constexpr int AITER = (BM * BK / 8) / THREADS;
    constexpr int BITER = (BK * BN / 8) / THREADS;

    #pragma unroll 1
    for (int k0 = 0; k0 < K; k0 += BK) {
        #pragma unroll
        for (int it = 0; it < AITER; it++) {
            int v = tid + it * THREADS;
            int r = v / (BK / 8);
            int q = v % (BK / 8);
            int grow = row0 + r;
            uint4 va = make_uint4(0, 0, 0, 0);
            if (grow < Nrows)
                va = *reinterpret_cast<const uint4*>(&g_h[(long)grow * K + k0 + q * 8]);
            *reinterpret_cast<uint4*>(&As[r][q * 8]) = va;
        }
        #pragma unroll
        for (int it = 0; it < BITER; it++) {
            int v = tid + it * THREADS;
            int r = v / (BN / 8);
            int q = v % (BN / 8);
            long gofs = (long)(k0 + r) * Mcols + col0 + q * 8;
            *reinterpret_cast<uint4*>(&Bs[0][r][q * 8]) =
                *reinterpret_cast<const uint4*>(&Whi[gofs]);
            *reinterpret_cast<uint4*>(&Bs[1][r][q * 8]) =
                *reinterpret_cast<const uint4*>(&Wlo[gofs]);
        }
        __syncthreads();

        #pragma unroll
        for (int k16 = 0; k16 < BK / 16; k16++) {
            uint32_t a[FM][4], bh[FN][2], bl[FN][2];
            const int arow = lane & 15;
            const int acol = k16 * 16 + ((lane >> 4) << 3);
            #pragma unroll
            for (int fm = 0; fm < FM; fm++)
                ldsm_x4(a[fm][0], a[fm][1], a[fm][2], a[fm][3],
                        sptr(&As[wm0 + fm * 16 + arow][acol]));
            const int brow = k16 * 16 + (lane & 15);
            const int bcofs = (lane >> 4) << 3;
            #pragma unroll
            for (int p = 0; p < FN / 2; p++) {
                ldsm_x4_t(bh[p * 2][0], bh[p * 2][1], bh[p * 2 + 1][0], bh[p * 2 + 1][1],
                          sptr(&Bs[0][brow][wn0 + p * 16 + bcofs]));
                ldsm_x4_t(bl[p * 2][0], bl[p * 2][1], bl[p * 2 + 1][0], bl[p * 2 + 1][1],
                          sptr(&Bs[1][brow][wn0 + p * 16 + bcofs]));
            }
            #pragma unroll
            for (int fm = 0; fm < FM; fm++)
                #pragma unroll
                for (int fn = 0; fn < FN; fn++) {
                    float* c = acc[fm][fn];
                    mma_f16(c[0], c[1], c[2], c[3],
                            a[fm][0], a[fm][1], a[fm][2], a[fm][3],
                            bh[fn][0], bh[fn][1]);
                    mma_f16(c[0], c[1], c[2], c[3],
                            a[fm][0], a[fm][1], a[fm][2], a[fm][3],
                            bl[fn][0], bl[fn][1]);
                }
        }
        __syncthreads();
    }

    #pragma unroll
    for (int fm = 0; fm < FM; fm++) {
        int grow0 = row0 + wm0 + fm * 16 + (lane >> 2);
        #pragma unroll
        for (int fn = 0; fn < FN; fn++) {
            int gcol = col0 + wn0 + fn * 8 + (lane & 3) * 2;
            float* c = acc[fm][fn];
            if (grow0 < Nrows)
                *reinterpret_cast<float2*>(&g_y[(long)grow0 * Mcols + gcol]) =
                    make_float2(c[0], c[1]);
            if (grow0 + 8 < Nrows)
                *reinterpret_cast<float2*>(&g_y[(long)(grow0 + 8) * Mcols + gcol]) =
                    make_float2(c[2], c[3]);
        }
    }
}

// ---------------- fp16 aggregate (256-wide): warp per node, x4 edge unroll -------------
__device__ __forceinline__ void h2f8(uint4 q, float* f) {
    const __half2* h = reinterpret_cast<const __half2*>(&q);
    float2 t;
    t = __half22float2(h[0]); f[0] = t.x; f[1] = t.y;
    t = __half22float2(h[1]); f[2] = t.x; f[3] = t.y;
    t = __half22float2(h[2]); f[4] = t.x; f[5] = t.y;
    t = __half22float2(h[3]); f[6] = t.x; f[7] = t.y;
}

__global__ void k_agg_h(const float* __restrict__ bias) {
    int warp = threadIdx.x >> 5, lane = threadIdx.x & 31;
    int node = blockIdx.x * 8 + warp;
    if (node >= NNODES) return;

    const uint4* __restrict__ qv = reinterpret_cast<const uint4*>(g_yh);

    float acc[8];
    {
        float4 b0 = *reinterpret_cast<const float4*>(bias + lane * 8);
        float4 b1 = *reinterpret_cast<const float4*>(bias + lane * 8 + 4);
        float sn = g_selfn[node];
        float f[8]; h2f8(qv[(long)node * 32 + lane], f);
        acc[0] = fmaf(sn, f[0], b0.x); acc[1] = fmaf(sn, f[1], b0.y);
        acc[2] = fmaf(sn, f[2], b0.z); acc[3] = fmaf(sn, f[3], b0.w);
        acc[4] = fmaf(sn, f[4], b1.x); acc[5] = fmaf(sn, f[5], b1.y);
        acc[6] = fmaf(sn, f[6], b1.z); acc[7] = fmaf(sn, f[7], b1.w);
    }

    int beg = g_off[node], end = g_off[node + 1];
    int j = beg;
    for (; j + 4 <= end; j += 4) {
        int   s0 = g_csr_src[j],     s1 = g_csr_src[j + 1];
        int   s2 = g_csr_src[j + 2], s3 = g_csr_src[j + 3];
        float w0 = g_csr_w[j],       w1 = g_csr_w[j + 1];
        float w2 = g_csr_w[j + 2],   w3 = g_csr_w[j + 3];
        uint4 q0 = qv[(long)s0 * 32 + lane];
        uint4 q1 = qv[(long)s1 * 32 + lane];
        uint4 q2 = qv[(long)s2 * 32 + lane];
        uint4 q3 = qv[(long)s3 * 32 + lane];
        float f[8];
        h2f8(q0, f);
        #pragma unroll
        for (int k = 0; k < 8; k++) acc[k] = fmaf(w0, f[k], acc[k]);
        h2f8(q1, f);
        #pragma unroll
        for (int k = 0; k < 8; k++) acc[k] = fmaf(w1, f[k], acc[k]);
        h2f8(q2, f);
        #pragma unroll
        for (int k = 0; k < 8; k++) acc[k] = fmaf(w2, f[k], acc[k]);
        h2f8(q3, f);
        #pragma unroll
        for (int k = 0; k < 8; k++) acc[k] = fmaf(w3, f[k], acc[k]);
    }
    for (; j < end; j++) {
        int   s = g_csr_src[j];
        float w = g_csr_w[j];
        float f[8]; h2f8(qv[(long)s * 32 + lane], f);
        #pragma unroll
        for (int k = 0; k < 8; k++) acc[k] = fmaf(w, f[k], acc[k]);
    }

    // relu + fp16 store
    uint4 O;
    __half2 p0 = __floats2half2_rn(fmaxf(acc[0], 0.f), fmaxf(acc[1], 0.f));
    __half2 p1 = __floats2half2_rn(fmaxf(acc[2], 0.f), fmaxf(acc[3], 0.f));
    __half2 p2 = __floats2half2_rn(fmaxf(acc[4], 0.f), fmaxf(acc[5], 0.f));
    __half2 p3 = __floats2half2_rn(fmaxf(acc[6], 0.f), fmaxf(acc[7], 0.f));
    O.x = *reinterpret_cast<uint32_t*>(&p0);
    O.y = *reinterpret_cast<uint32_t*>(&p1);
    O.z = *reinterpret_cast<uint32_t*>(&p2);
    O.w = *reinterpret_cast<uint32_t*>(&p3);
    reinterpret_cast<uint4*>(g_h)[(long)node * 32 + lane] = O;
}

// ---------------- Final aggregate (32-wide, fp32 gathers, tanh) ----------------
__global__ void k_agg_out(const float* __restrict__ bias, float* __restrict__ outp) {
    constexpr int TPN = NCLS / 4;
    constexpr int NPB = 256 / TPN;
    int node = blockIdx.x * NPB + threadIdx.x / TPN;
    if (node >= NNODES) return;
    int t = threadIdx.x % TPN;

    const float4* __restrict__ yv = reinterpret_cast<const float4*>(g_y);
    float4 self = yv[(long)node * TPN + t];
    float  sn   = g_selfn[node];
    float4 bv   = reinterpret_cast<const float4*>(bias)[t];

    float4 acc;
    acc.x = fmaf(sn, self.x, bv.x);
    acc.y = fmaf(sn, self.y, bv.y);
    acc.z = fmaf(sn, self.z, bv.z);
    acc.w = fmaf(sn, self.w, bv.w);

    int beg = g_off[node], end = g_off[node + 1];
    int j = beg;
    for (; j + 2 <= end; j += 2) {
        int   s0 = __ldg(&g_csr_src[j]),   s1 = __ldg(&g_csr_src[j + 1]);
        float w0 = __ldg(&g_csr_w[j]),     w1 = __ldg(&g_csr_w[j + 1]);
        float4 v0 = yv[(long)s0 * TPN + t];
        float4 v1 = yv[(long)s1 * TPN + t];
        acc.x = fmaf(w0, v0.x, acc.x); acc.y = fmaf(w0, v0.y, acc.y);
        acc.z = fmaf(w0, v0.z, acc.z); acc.w = fmaf(w0, v0.w, acc.w);
        acc.x = fmaf(w1, v1.x, acc.x); acc.y = fmaf(w1, v1.y, acc.y);
        acc.z = fmaf(w1, v1.z, acc.z); acc.w = fmaf(w1, v1.w, acc.w);
    }
    for (; j < end; j++) {
        int   s = __ldg(&g_csr_src[j]);
        float w = __ldg(&g_csr_w[j]);
        float4 v = yv[(long)s * TPN + t];
        acc.x = fmaf(w, v.x, acc.x);
        acc.y = fmaf(w, v.y, acc.y);
        acc.z = fmaf(w, v.z, acc.z);
        acc.w = fmaf(w, v.w, acc.w);
    }
    acc.x = tanhf(acc.x); acc.y = tanhf(acc.y);
    acc.z = tanhf(acc.z); acc.w = tanhf(acc.w);
    reinterpret_cast<float4*>(outp)[(long)node * TPN + t] = acc;
}

// ---------------- Launch ----------------
extern "C" void kernel_launch(void* const* d_in, const int* in_sizes, int n_in,
                              void* d_out, int out_size) {
    const float* x     = (const float*)d_in[0];
    const int*   ei    = (const int*)d_in[1];
    const float* W_in  = (const float*)d_in[2];
    const float* b_in  = (const float*)d_in[3];
    const float* W_h   = (const float*)d_in[4];
    const float* b_h   = (const float*)d_in[5];
    const float* W_out = (const float*)d_in[6];
    const float* b_out = (const float*)d_in[7];
    float* out = (float*)d_out;

    const int* src = ei;
    const int* dst = ei + NEDGES;

    const int nthreads = 256;
    const int nblk_nodes = (NNODES + nthreads - 1) / nthreads;
    const int nblk_edges = (NEDGES + nthreads - 1) / nthreads;

    // dynamic smem: (2*128*40 + 4*32*136) halves = 27648 halves = 55296 bytes
    const int GP_SMEM = (2 * 128 * 40 + 4 * 32 * 136) * 2;
    cudaFuncSetAttribute(mma_gemm_p, cudaFuncAttributeMaxDynamicSharedMemorySize, GP_SMEM);

    dim3 gemmH_grid(HID / 128, (NNODES + 127) / 128);
    dim3 gemmO_grid(1, (NNODES + 127) / 128);
    const int agg_blocks  = (NNODES + 7) / 8;
    const int aggo_blocks = (NNODES + 31) / 32;

    // ---- splits + GEMM0 early (profiler lands on the big GEMM) ----
    k_split_w_all<<<(WSZ_TOT / 4 + 255) / 256, 256>>>(W_in, W_h, W_out);              // 1
    k_cvt_x<<<(NNODES * FIN / 4 + 255) / 256, 256>>>(x, NNODES * FIN);                // 2
    k_zero_counts<<<nblk_nodes, nthreads>>>();                                        // 3
    mma_gemm_p<<<gemmH_grid, 256, GP_SMEM>>>(NNODES, FIN, HID, 0);                    // 4 (GEMM0)

    // ---- preprocessing ----
    k_hist<<<nblk_edges, nthreads>>>(dst);
    k_blksum<<<NB512, 512>>>();
    k_blkscan<<<1, 128>>>();
    k_scanfinal<<<NB512, 512>>>();
    k_fill_csr<<<nblk_edges, nthreads>>>(src, dst);

    // ---- layers ----
    k_agg_h<<<agg_blocks, 256>>>(b_in);
    mma_gemm_p<<<gemmH_grid, 256, GP_SMEM>>>(NNODES, HID, HID, W_OFF_H);
    k_agg_h<<<agg_blocks, 256>>>(b_h);
    mma_gemm_p<<<gemmH_grid, 256, GP_SMEM>>>(NNODES, HID, HID, W_OFF_H + 256 * 256);
    k_agg_h<<<agg_blocks, 256>>>(b_h + HID);
    mma_gemm_s<128, 32, 32, 32><<<gemmO_grid, 128>>>(NNODES, HID, NCLS, W_OFF_OUT);
    k_agg_out<<<aggo_blocks, 256>>>(b_out, out);

    (void)in_sizes; (void)n_in; (void)out_size;
}

// round 11
// speedup vs baseline: 1.0194x; 1.0194x over previous
#include <cuda_runtime.h>
#include <cuda_bf16.h>
#include <cuda_fp16.h>
#include <math.h>
#include <stdint.h>

// Problem constants (fixed-shape problem)
#define NNODES 50000
#define NEDGES 800000
#define FIN    256
#define HID    256
#define NCLS   32
#define SELFW  2.0f

#define WSZ_TOT (3*256*256 + 256*32)     // all weights, fp16 split storage
#define W_OFF_H   (256*256)
#define W_OFF_OUT (3*256*256)

// ---------------- Device scratch (no allocations allowed) ----------------
__device__ int   g_deg[NNODES];
__device__ int   g_cur[NNODES];
__device__ int   g_off[NNODES];
__device__ int   g_counter;
__device__ __align__(16) int   g_csr_src[NEDGES];
__device__ __align__(16) float g_csr_w[NEDGES];
__device__ float g_dinv[NNODES];
__device__ float g_selfn[NNODES];
__device__ __align__(16) float  g_y[NNODES * NCLS];     // fp32 GEMM out (final layer)
__device__ __align__(16) __half g_yh[NNODES * HID];     // fp16 GEMM out / gather plane
__device__ __align__(16) __half g_h[NNODES * HID];      // fp16 activations (GEMM A input)
__device__ __align__(16) __half g_Whi[WSZ_TOT];         // weight hi split (fp16)
__device__ __align__(16) __half g_Wlo[WSZ_TOT];         // weight lo split (fp16)

// ---------------- small helpers ----------------
__device__ __forceinline__ uint32_t sptr(const void* p) {
    return (uint32_t)__cvta_generic_to_shared(p);
}
__device__ __forceinline__ void ldsm_x4(uint32_t& r0, uint32_t& r1, uint32_t& r2, uint32_t& r3,
                                        uint32_t addr) {
    asm volatile("ldmatrix.sync.aligned.m8n8.x4.shared.b16 {%0,%1,%2,%3}, [%4];\n"
                 : "=r"(r0), "=r"(r1), "=r"(r2), "=r"(r3) : "r"(addr));
}
__device__ __forceinline__ void ldsm_x4_t(uint32_t& r0, uint32_t& r1, uint32_t& r2, uint32_t& r3,
                                          uint32_t addr) {
    asm volatile("ldmatrix.sync.aligned.m8n8.x4.trans.shared.b16 {%0,%1,%2,%3}, [%4];\n"
                 : "=r"(r0), "=r"(r1), "=r"(r2), "=r"(r3) : "r"(addr));
}
__device__ __forceinline__ void mma_f16(float& c0, float& c1, float& c2, float& c3,
                                        uint32_t a0, uint32_t a1, uint32_t a2, uint32_t a3,
                                        uint32_t b0, uint32_t b1) {
    asm volatile("mma.sync.aligned.m16n8k16.row.col.f32.f16.f16.f32 "
                 "{%0,%1,%2,%3}, {%4,%5,%6,%7}, {%8,%9}, {%0,%1,%2,%3};\n"
                 : "+f"(c0), "+f"(c1), "+f"(c2), "+f"(c3)
                 : "r"(a0), "r"(a1), "r"(a2), "r"(a3), "r"(b0), "r"(b1));
}
__device__ __forceinline__ void cp16(uint32_t saddr, const void* g, int sz) {
    asm volatile("cp.async.cg.shared.global [%0], [%1], 16, %2;\n"
                 :: "r"(saddr), "l"(g), "r"(sz));
}
__device__ __forceinline__ void cp_commit() { asm volatile("cp.async.commit_group;\n"); }
template <int N>
__device__ __forceinline__ void cp_wait() { asm volatile("cp.async.wait_group %0;\n" :: "n"(N)); }

// ---------------- fp32 -> fp16 hi/lo split ----------------
__device__ __forceinline__ void wsplit2(float a, float b, __half2& h2, __half2& l2) {
    __half ha = __float2half_rn(a);
    __half hb = __float2half_rn(b);
    __half la = __float2half_rn(a - __half2float(ha));
    __half lb = __float2half_rn(b - __half2float(hb));
    h2 = __half2(ha, hb);
    l2 = __half2(la, lb);
}

// ---------------- weight split (all weights, one kernel) ----------------
__global__ void k_split_w_all(const float* __restrict__ Win,
                              const float* __restrict__ Wh,
                              const float* __restrict__ Wout) {
    int i = blockIdx.x * blockDim.x + threadIdx.x;   // vec4 index
    int e4 = i * 4;
    if (e4 >= WSZ_TOT) return;
    const float* src;
    int off;
    if (e4 < W_OFF_H)        { src = Win;  off = e4; }
    else if (e4 < W_OFF_OUT) { src = Wh;   off = e4 - W_OFF_H; }
    else                     { src = Wout; off = e4 - W_OFF_OUT; }
    float4 v = *reinterpret_cast<const float4*>(src + off);
    __half2 h0, l0, h1, l1;
    wsplit2(v.x, v.y, h0, l0);
    wsplit2(v.z, v.w, h1, l1);
    __half2* H = reinterpret_cast<__half2*>(g_Whi);
    __half2* L = reinterpret_cast<__half2*>(g_Wlo);
    H[i * 2] = h0; H[i * 2 + 1] = h1;
    L[i * 2] = l0; L[i * 2 + 1] = l1;
}

// ---------------- Precompute: degree, norm, CSR ----------------
__global__ void k_zero_counts() {
    int i = blockIdx.x * blockDim.x + threadIdx.x;
    if (i < NNODES) { g_deg[i] = 0; g_cur[i] = 0; }
    if (i == 0) g_counter = 0;
}

__global__ void k_hist(const int* __restrict__ dst) {
    int e = blockIdx.x * blockDim.x + threadIdx.x;
    if (e < NEDGES) atomicAdd(&g_deg[dst[e]], 1);
}

// dinv/selfn + CSR offsets in ONE kernel: per-warp atomic base + warp scan.
// Bucket order across warps is arbitrary (doesn't matter for CSR correctness).
__global__ void k_offsets() {
    int i = blockIdx.x * blockDim.x + threadIdx.x;
    int lane = threadIdx.x & 31;
    int v = 0;
    if (i < NNODES) {
        v = g_deg[i];
        float d  = (float)v + SELFW;
        float di = rsqrtf(d);
        g_dinv[i]  = di;
        g_selfn[i] = SELFW * di * di;
    }
    int incl = v;
    #pragma unroll
    for (int o = 1; o < 32; o <<= 1) {
        int y = __shfl_up_sync(0xffffffffu, incl, o);
        if (lane >= o) incl += y;
    }
    int tot = __shfl_sync(0xffffffffu, incl, 31);
    int base = 0;
    if (lane == 0) base = atomicAdd(&g_counter, tot);
    base = __shfl_sync(0xffffffffu, base, 0);
    if (i < NNODES) g_off[i] = base + incl - v;
}

__global__ void k_fill_csr(const int* __restrict__ src, const int* __restrict__ dst) {
    int e = blockIdx.x * blockDim.x + threadIdx.x;
    if (e < NEDGES) {
        int s = src[e], d = dst[e];
        int p = atomicAdd(&g_cur[d], 1);
        int idx = g_off[d] + p;
        g_csr_src[idx] = s;
        g_csr_w[idx]   = g_dinv[s] * g_dinv[d];
    }
}

// ---------------- fp16 2-term split GEMM, cp.async 2-stage pipeline (big layers) -------
// C_fp16[Nrows,256] = A @ (Whi + Wlo); BM=128, BN=128, 256 thr.
// CVT=0: A = g_h (fp16, cp.async). CVT=1: A = Aext (fp32), in-register convert (layer 0).
template <int CVT>
__global__ void __launch_bounds__(256) mma_gemm_p(int Nrows, int K, int Mcols, int woff,
                                                  const float* __restrict__ Aext) {
    constexpr int BM = 128, BN = 128, BK = 32;
    constexpr int WM = 64, WN = 32;
    constexpr int WARPS_N = BN / WN;          // 4
    constexpr int FM = WM / 16;               // 4
    constexpr int FN = WN / 8;                // 4
    constexpr int ASTR = BK + 8;              // 40 halves (80B rows, 16B aligned)
    constexpr int BSTR = BN + 8;              // 136 halves
    constexpr int A_ST = BM * ASTR;           // per stage
    constexpr int B_ST = BK * BSTR;           // per stage-plane

    extern __shared__ __half sm[];
    __half* Asm = sm;                         // [st][BM][ASTR]
    __half* Bsm = sm + 2 * A_ST;              // [st][plane][BK][BSTR]

    const int tid  = threadIdx.x;
    const int lane = tid & 31;
    const int w    = tid >> 5;
    const int wm0  = (w / WARPS_N) * WM;
    const int wn0  = (w % WARPS_N) * WN;
    const int row0 = blockIdx.y * BM;
    const int col0 = blockIdx.x * BN;

    const __half* __restrict__ Whi = g_Whi + woff;
    const __half* __restrict__ Wlo = g_Wlo + woff;

    float acc[FM][FN][4];
    #pragma unroll
    for (int i = 0; i < FM; i++)
        #pragma unroll
        for (int j = 0; j < FN; j++)
            #pragma unroll
            for (int r = 0; r < 4; r++) acc[i][j][r] = 0.f;

    const int NT = K / BK;   // 8

    auto issue = [&](int kt, int st) {
        int k0 = kt * BK;
        // A: 128 rows x 4 vec8 = 512 units, 2 iters
        #pragma unroll
        for (int it = 0; it < 2; it++) {
            int u = tid + it * 256;
            int r = u >> 2, q = u & 3;
            int grow = row0 + r;
            if (CVT) {
                float4 f0 = make_float4(0.f, 0.f, 0.f, 0.f);
                float4 f1 = make_float4(0.f, 0.f, 0.f, 0.f);
                if (grow < Nrows) {
                    const float4* xp = reinterpret_cast<const float4*>(
                        Aext + (long)grow * K + k0 + q * 8);
                    f0 = xp[0];
                    f1 = xp[1];
                }
                __half2 h0 = __floats2half2_rn(f0.x, f0.y);
                __half2 h1 = __floats2half2_rn(f0.z, f0.w);
                __half2 h2 = __floats2half2_rn(f1.x, f1.y);
                __half2 h3 = __floats2half2_rn(f1.z, f1.w);
                uint4 pk;
                pk.x = *reinterpret_cast<uint32_t*>(&h0);
                pk.y = *reinterpret_cast<uint32_t*>(&h1);
                pk.z = *reinterpret_cast<uint32_t*>(&h2);
                pk.w = *reinterpret_cast<uint32_t*>(&h3);
                *reinterpret_cast<uint4*>(Asm + st * A_ST + r * ASTR + q * 8) = pk;
            } else {
                int sz = (grow < Nrows) ? 16 : 0;
                long ga = (long)((grow < Nrows) ? grow : 0) * K + k0 + q * 8;
                cp16(sptr(Asm + st * A_ST + r * ASTR + q * 8), g_h + ga, sz);
            }
        }
        // B planes: 32 rows x 16 vec8 = 512 units each, 2 iters each
        #pragma unroll
        for (int it = 0; it < 2; it++) {
            int u = tid + it * 256;
            int r = u >> 4, q = u & 15;
            long gb = (long)(k0 + r) * Mcols + col0 + q * 8;
            cp16(sptr(Bsm + (st * 2 + 0) * B_ST + r * BSTR + q * 8), Whi + gb, 16);
            cp16(sptr(Bsm + (st * 2 + 1) * B_ST + r * BSTR + q * 8), Wlo + gb, 16);
        }
        cp_commit();
    };

    issue(0, 0);

    #pragma unroll 1
    for (int kt = 0; kt < NT; kt++) {
        int st = kt & 1;
        if (kt + 1 < NT) { issue(kt + 1, st ^ 1); cp_wait<1>(); }
        else             { cp_wait<0>(); }
        __syncthreads();

        #pragma unroll
        for (int k16 = 0; k16 < BK / 16; k16++) {
            uint32_t a[FM][4], bh[FN][2], bl[FN][2];
            const int arow = lane & 15;
            const int acol = k16 * 16 + ((lane >> 4) << 3);
            #pragma unroll
            for (int fm = 0; fm < FM; fm++)
                ldsm_x4(a[fm][0], a[fm][1], a[fm][2], a[fm][3],
                        sptr(Asm + st * A_ST + (wm0 + fm * 16 + arow) * ASTR + acol));
            const int brow = k16 * 16 + (lane & 15);
            const int bcofs = (lane >> 4) << 3;
            #pragma unroll
            for (int p = 0; p < FN / 2; p++) {
                ldsm_x4_t(bh[p * 2][0], bh[p * 2][1], bh[p * 2 + 1][0], bh[p * 2 + 1][1],
                          sptr(Bsm + (st * 2 + 0) * B_ST + brow * BSTR + wn0 + p * 16 + bcofs));
                ldsm_x4_t(bl[p * 2][0], bl[p * 2][1], bl[p * 2 + 1][0], bl[p * 2 + 1][1],
                          sptr(Bsm + (st * 2 + 1) * B_ST + brow * BSTR + wn0 + p * 16 + bcofs));
            }
            #pragma unroll
            for (int fm = 0; fm < FM; fm++)
                #pragma unroll
                for (int fn = 0; fn < FN; fn++) {
                    float* c = acc[fm][fn];
                    mma_f16(c[0], c[1], c[2], c[3],
                            a[fm][0], a[fm][1], a[fm][2], a[fm][3],
                            bh[fn][0], bh[fn][1]);
                    mma_f16(c[0], c[1], c[2], c[3],
                            a[fm][0], a[fm][1], a[fm][2], a[fm][3],
                            bl[fn][0], bl[fn][1]);
                }
        }
        __syncthreads();
    }

    // epilogue -> fp16 g_yh
    #pragma unroll
    for (int fm = 0; fm < FM; fm++) {
        int grow0 = row0 + wm0 + fm * 16 + (lane >> 2);
        #pragma unroll
        for (int fn = 0; fn < FN; fn++) {
            int gcol = col0 + wn0 + fn * 8 + (lane & 3) * 2;
            float* c = acc[fm][fn];
            if (grow0 < Nrows)
                *reinterpret_cast<__half2*>(&g_yh[(long)grow0 * Mcols + gcol]) =
                    __floats2half2_rn(c[0], c[1]);
            if (grow0 + 8 < Nrows)
                *reinterpret_cast<__half2*>(&g_yh[(long)(grow0 + 8) * Mcols + gcol]) =
                    __floats2half2_rn(c[2], c[3]);
        }
    }
}

// ---------------- fp16 2-term split GEMM (sync smem; out layer, fp32 out) --------------
template <int BM, int BN, int WM, int WN>
__global__ void mma_gemm_s(int Nrows, int K, int Mcols, int woff) {
    constexpr int WARPS_M = BM / WM;
    constexpr int WARPS_N = BN / WN;
    constexpr int THREADS = WARPS_M * WARPS_N * 32;
    constexpr int FM = WM / 16;
    constexpr int FN = WN / 8;
    constexpr int BK = 32;

    __shared__ __half As[BM][BK + 8];
    __shared__ __half Bs[2][BK][BN + 8];

    const int tid  = threadIdx.x;
    const int lane = tid & 31;
    const int w    = tid >> 5;
    const int wm0  = (w / WARPS_N) * WM;
    const int wn0  = (w % WARPS_N) * WN;
    const int row0 = blockIdx.y * BM;
    const int col0 = blockIdx.x * BN;

    const __half* __restrict__ Whi = g_Whi + woff;
    const __half* __restrict__ Wlo = g_Wlo + woff;

    float acc[FM][FN][4];
    #pragma unroll
    for (int i = 0; i < FM; i++)
        #pragma unroll
        for (int j = 0; j < FN; j++)
            #pragma unroll
            for (int r = 0; r < 4; r++) acc[i][j][r] = 0.f;

    constexpr int AITER = (BM * BK / 8) / THREADS;
    constexpr int BITER = (BK * BN / 8) / THREADS;

    #pragma unroll 1
    for (int k0 = 0; k0 < K; k0 += BK) {
        #pragma unroll
        for (int it = 0; it < AITER; it++) {
            int v = tid + it * THREADS;
            int r = v / (BK / 8);
            int q = v % (BK / 8);
            int grow = row0 + r;
            uint4 va = make_uint4(0, 0, 0, 0);
            if (grow < Nrows)
                va = *reinterpret_cast<const uint4*>(&g_h[(long)grow * K + k0 + q * 8]);
            *reinterpret_cast<uint4*>(&As[r][q * 8]) = va;
        }
        #pragma unroll
        for (int it = 0; it < BITER; it++) {
            int v = tid + it * THREADS;
            int r = v / (BN / 8);
            int q = v % (BN / 8);
            long gofs = (long)(k0 + r) * Mcols + col0 + q * 8;
            *reinterpret_cast<uint4*>(&Bs[0][r][q * 8]) =
                *reinterpret_cast<const uint4*>(&Whi[gofs]);
            *reinterpret_cast<uint4*>(&Bs[1][r][q * 8]) =
                *reinterpret_cast<const uint4*>(&Wlo[gofs]);
        }
        __syncthreads();

        #pragma unroll
        for (int k16 = 0; k16 < BK / 16; k16++) {
            uint32_t a[FM][4], bh[FN][2], bl[FN][2];
            const int arow = lane & 15;
            const int acol = k16 * 16 + ((lane >> 4) << 3);
            #pragma unroll
            for (int fm = 0; fm < FM; fm++)
                ldsm_x4(a[fm][0], a[fm][1], a[fm][2], a[fm][3],
                        sptr(&As[wm0 + fm * 16 + arow][acol]));
            const int brow = k16 * 16 + (lane & 15);
            const int bcofs = (lane >> 4) << 3;
            #pragma unroll
            for (int p = 0; p < FN / 2; p++) {
                ldsm_x4_t(bh[p * 2][0], bh[p * 2][1], bh[p * 2 + 1][0], bh[p * 2 + 1][1],
                          sptr(&Bs[0][brow][wn0 + p * 16 + bcofs]));
                ldsm_x4_t(bl[p * 2][0], bl[p * 2][1], bl[p * 2 + 1][0], bl[p * 2 + 1][1],
                          sptr(&Bs[1][brow][wn0 + p * 16 + bcofs]));
            }
            #pragma unroll
            for (int fm = 0; fm < FM; fm++)
                #pragma unroll
                for (int fn = 0; fn < FN; fn++) {
                    float* c = acc[fm][fn];
                    mma_f16(c[0], c[1], c[2], c[3],
                            a[fm][0], a[fm][1], a[fm][2], a[fm][3],
                            bh[fn][0], bh[fn][1]);
                    mma_f16(c[0], c[1], c[2], c[3],
                            a[fm][0], a[fm][1], a[fm][2], a[fm][3],
                            bl[fn][0], bl[fn][1]);
                }
        }
        __syncthreads();
    }

    #pragma unroll
    for (int fm = 0; fm < FM; fm++) {
        int grow0 = row0 + wm0 + fm * 16 + (lane >> 2);
        #pragma unroll
        for (int fn = 0; fn < FN; fn++) {
            int gcol = col0 + wn0 + fn * 8 + (lane & 3) * 2;
            float* c = acc[fm][fn];
            if (grow0 < Nrows)
                *reinterpret_cast<float2*>(&g_y[(long)grow0 * Mcols + gcol]) =
                    make_float2(c[0], c[1]);
            if (grow0 + 8 < Nrows)
                *reinterpret_cast<float2*>(&g_y[(long)(grow0 + 8) * Mcols + gcol]) =
                    make_float2(c[2], c[3]);
        }
    }
}

// ---------------- fp16 aggregate (256-wide): warp per node, x4 edge unroll -------------
__device__ __forceinline__ void h2f8(uint4 q, float* f) {
    const __half2* h = reinterpret_cast<const __half2*>(&q);
    float2 t;
    t = __half22float2(h[0]); f[0] = t.x; f[1] = t.y;
    t = __half22float2(h[1]); f[2] = t.x; f[3] = t.y;
    t = __half22float2(h[2]); f[4] = t.x; f[5] = t.y;
    t = __half22float2(h[3]); f[6] = t.x; f[7] = t.y;
}

__global__ void k_agg_h(const float* __restrict__ bias) {
    int warp = threadIdx.x >> 5, lane = threadIdx.x & 31;
    int node = blockIdx.x * 8 + warp;
    if (node >= NNODES) return;

    const uint4* __restrict__ qv = reinterpret_cast<const uint4*>(g_yh);

    float acc[8];
    {
        float4 b0 = *reinterpret_cast<const float4*>(bias + lane * 8);
        float4 b1 = *reinterpret_cast<const float4*>(bias + lane * 8 + 4);
        float sn = g_selfn[node];
        float f[8]; h2f8(qv[(long)node * 32 + lane], f);
        acc[0] = fmaf(sn, f[0], b0.x); acc[1] = fmaf(sn, f[1], b0.y);
        acc[2] = fmaf(sn, f[2], b0.z); acc[3] = fmaf(sn, f[3], b0.w);
        acc[4] = fmaf(sn, f[4], b1.x); acc[5] = fmaf(sn, f[5], b1.y);
        acc[6] = fmaf(sn, f[6], b1.z); acc[7] = fmaf(sn, f[7], b1.w);
    }

    int beg = g_off[node], end = beg + g_deg[node];
    int j = beg;
    for (; j + 4 <= end; j += 4) {
        int   s0 = g_csr_src[j],     s1 = g_csr_src[j + 1];
        int   s2 = g_csr_src[j + 2], s3 = g_csr_src[j + 3];
        float w0 = g_csr_w[j],       w1 = g_csr_w[j + 1];
        float w2 = g_csr_w[j + 2],   w3 = g_csr_w[j + 3];
        uint4 q0 = qv[(long)s0 * 32 + lane];
        uint4 q1 = qv[(long)s1 * 32 + lane];
        uint4 q2 = qv[(long)s2 * 32 + lane];
        uint4 q3 = qv[(long)s3 * 32 + lane];
        float f[8];
        h2f8(q0, f);
        #pragma unroll
        for (int k = 0; k < 8; k++) acc[k] = fmaf(w0, f[k], acc[k]);
        h2f8(q1, f);
        #pragma unroll
        for (int k = 0; k < 8; k++) acc[k] = fmaf(w1, f[k], acc[k]);
        h2f8(q2, f);
        #pragma unroll
        for (int k = 0; k < 8; k++) acc[k] = fmaf(w2, f[k], acc[k]);
        h2f8(q3, f);
        #pragma unroll
        for (int k = 0; k < 8; k++) acc[k] = fmaf(w3, f[k], acc[k]);
    }
    for (; j < end; j++) {
        int   s = g_csr_src[j];
        float w = g_csr_w[j];
        float f[8]; h2f8(qv[(long)s * 32 + lane], f);
        #pragma unroll
        for (int k = 0; k < 8; k++) acc[k] = fmaf(w, f[k], acc[k]);
    }

    // relu + fp16 store
    uint4 O;
    __half2 p0 = __floats2half2_rn(fmaxf(acc[0], 0.f), fmaxf(acc[1], 0.f));
    __half2 p1 = __floats2half2_rn(fmaxf(acc[2], 0.f), fmaxf(acc[3], 0.f));
    __half2 p2 = __floats2half2_rn(fmaxf(acc[4], 0.f), fmaxf(acc[5], 0.f));
    __half2 p3 = __floats2half2_rn(fmaxf(acc[6], 0.f), fmaxf(acc[7], 0.f));
    O.x = *reinterpret_cast<uint32_t*>(&p0);
    O.y = *reinterpret_cast<uint32_t*>(&p1);
    O.z = *reinterpret_cast<uint32_t*>(&p2);
    O.w = *reinterpret_cast<uint32_t*>(&p3);
    reinterpret_cast<uint4*>(g_h)[(long)node * 32 + lane] = O;
}

// ---------------- Final aggregate (32-wide, fp32 gathers, tanh) ----------------
__global__ void k_agg_out(const float* __restrict__ bias, float* __restrict__ outp) {
    constexpr int TPN = NCLS / 4;
    constexpr int NPB = 256 / TPN;
    int node = blockIdx.x * NPB + threadIdx.x / TPN;
    if (node >= NNODES) return;
    int t = threadIdx.x % TPN;

    const float4* __restrict__ yv = reinterpret_cast<const float4*>(g_y);
    float4 self = yv[(long)node * TPN + t];
    float  sn   = g_selfn[node];
    float4 bv   = reinterpret_cast<const float4*>(bias)[t];

    float4 acc;
    acc.x = fmaf(sn, self.x, bv.x);
    acc.y = fmaf(sn, self.y, bv.y);
    acc.z = fmaf(sn, self.z, bv.z);
    acc.w = fmaf(sn, self.w, bv.w);

    int beg = g_off[node], end = beg + g_deg[node];
    int j = beg;
    for (; j + 2 <= end; j += 2) {
        int   s0 = __ldg(&g_csr_src[j]),   s1 = __ldg(&g_csr_src[j + 1]);
        float w0 = __ldg(&g_csr_w[j]),     w1 = __ldg(&g_csr_w[j + 1]);
        float4 v0 = yv[(long)s0 * TPN + t];
        float4 v1 = yv[(long)s1 * TPN + t];
        acc.x = fmaf(w0, v0.x, acc.x); acc.y = fmaf(w0, v0.y, acc.y);
        acc.z = fmaf(w0, v0.z, acc.z); acc.w = fmaf(w0, v0.w, acc.w);
        acc.x = fmaf(w1, v1.x, acc.x); acc.y = fmaf(w1, v1.y, acc.y);
        acc.z = fmaf(w1, v1.z, acc.z); acc.w = fmaf(w1, v1.w, acc.w);
    }
    for (; j < end; j++) {
        int   s = __ldg(&g_csr_src[j]);
        float w = __ldg(&g_csr_w[j]);
        float4 v = yv[(long)s * TPN + t];
        acc.x = fmaf(w, v.x, acc.x);
        acc.y = fmaf(w, v.y, acc.y);
        acc.z = fmaf(w, v.z, acc.z);
        acc.w = fmaf(w, v.w, acc.w);
    }
    acc.x = tanhf(acc.x); acc.y = tanhf(acc.y);
    acc.z = tanhf(acc.z); acc.w = tanhf(acc.w);
    reinterpret_cast<float4*>(outp)[(long)node * TPN + t] = acc;
}

// ---------------- Launch ----------------
extern "C" void kernel_launch(void* const* d_in, const int* in_sizes, int n_in,
                              void* d_out, int out_size) {
    const float* x     = (const float*)d_in[0];
    const int*   ei    = (const int*)d_in[1];
    const float* W_in  = (const float*)d_in[2];
    const float* b_in  = (const float*)d_in[3];
    const float* W_h   = (const float*)d_in[4];
    const float* b_h   = (const float*)d_in[5];
    const float* W_out = (const float*)d_in[6];
    const float* b_out = (const float*)d_in[7];
    float* out = (float*)d_out;

    const int* src = ei;
    const int* dst = ei + NEDGES;

    const int nthreads = 256;
    const int nblk_nodes = (NNODES + nthreads - 1) / nthreads;
    const int nblk_edges = (NEDGES + nthreads - 1) / nthreads;

    // dynamic smem: (2*128*40 + 4*32*136) halves = 55296 bytes
    const int GP_SMEM = (2 * 128 * 40 + 4 * 32 * 136) * 2;
    cudaFuncSetAttribute(mma_gemm_p<0>, cudaFuncAttributeMaxDynamicSharedMemorySize, GP_SMEM);
    cudaFuncSetAttribute(mma_gemm_p<1>, cudaFuncAttributeMaxDynamicSharedMemorySize, GP_SMEM);

    dim3 gemmH_grid(HID / 128, (NNODES + 127) / 128);
    dim3 gemmO_grid(1, (NNODES + 127) / 128);
    const int agg_blocks  = (NNODES + 7) / 8;
    const int aggo_blocks = (NNODES + 31) / 32;

    // ---- setup + GEMM0 (fused x-convert) early ----
    k_split_w_all<<<(WSZ_TOT / 4 + 255) / 256, 256>>>(W_in, W_h, W_out);           // 1
    k_zero_counts<<<nblk_nodes, nthreads>>>();                                     // 2
    mma_gemm_p<1><<<gemmH_grid, 256, GP_SMEM>>>(NNODES, FIN, HID, 0, x);           // 3 (GEMM0)

    // ---- preprocessing ----
    k_hist<<<nblk_edges, nthreads>>>(dst);
    k_offsets<<<nblk_nodes, nthreads>>>();
    k_fill_csr<<<nblk_edges, nthreads>>>(src, dst);

    // ---- layers ----
    k_agg_h<<<agg_blocks, 256>>>(b_in);
    mma_gemm_p<0><<<gemmH_grid, 256, GP_SMEM>>>(NNODES, HID, HID, W_OFF_H, nullptr);
    k_agg_h<<<agg_blocks, 256>>>(b_h);
    mma_gemm_p<0><<<gemmH_grid, 256, GP_SMEM>>>(NNODES, HID, HID, W_OFF_H + 256 * 256, nullptr);
    k_agg_h<<<agg_blocks, 256>>>(b_h + HID);
    mma_gemm_s<128, 32, 32, 32><<<gemmO_grid, 128>>>(NNODES, HID, NCLS, W_OFF_OUT);
    k_agg_out<<<aggo_blocks, 256>>>(b_out, out);

    (void)in_sizes; (void)n_in; (void)out_size;
}